// round 15
// baseline (speedup 1.0000x reference)
#include <cuda_runtime.h>
#include <math.h>

#define B 8
#define TE 12
#define TD 12
#define CIN 16
#define HD 96
#define COUT 8
#define CD 104   /* COUT + HD */
#define CE 112   /* CIN + HD */
#define HW 4096
#define NSTATE (B*HD*HW)   /* 3,145,728 */

// ---- scratch (device globals: no allocation in kernel_launch) ----
__device__ float g_c[NSTATE];
__device__ float g_hA[NSTATE];
__device__ float g_hB[NSTATE];
__device__ float g_hhist[13][NSTATE];   // [0]=encoder final h, [t+1]=decoder h_t
__device__ float g_Kp[COUT*HD*9];       // folded oK∘lW
__device__ float g_bp[COUT];

__device__ __forceinline__ float sigmf(float x) { return 1.0f/(1.0f + expf(-x)); }

// ---------------------------------------------------------------- zero init
__global__ void zero_kernel() {
    int n4 = NSTATE/4;
    float4 z = make_float4(0.f,0.f,0.f,0.f);
    for (int i = blockIdx.x*blockDim.x + threadIdx.x; i < n4; i += gridDim.x*blockDim.x) {
        ((float4*)g_c)[i]  = z;
        ((float4*)g_hA)[i] = z;
    }
}

// ---------------------------------------------------------------- fold output head
// Kp[oc][hc][tap] = sum_c lW[c,oc]*oK[c,hc,tap];  bp[oc] = sum_c lW[c,oc]*ob[c] + lb[oc]
__global__ void kp_kernel(const float* __restrict__ lW, const float* __restrict__ oK,
                          const float* __restrict__ ob, const float* __restrict__ lb) {
    int idx = blockIdx.x*blockDim.x + threadIdx.x;
    if (idx < COUT*HD*9) {
        int oc  = idx / (HD*9);
        int rem = idx - oc*(HD*9);     // = hc*9 + tap
        float s = 0.f;
        for (int c = 0; c < CD; c++)
            s += lW[c*COUT + oc] * oK[c*HD*9 + rem];
        g_Kp[idx] = s;
    }
    if (idx < COUT) {
        float s = lb[idx];
        for (int c = 0; c < CD; c++) s += lW[c*COUT + idx]*ob[c];
        g_bp[idx] = s;
    }
}

// ---------------------------------------------------------------- encoder step
// gates[d,p] = sum_{c<112} W_g[c,d] * xc[c,p],  xc = [enc_in[b,t] ; h]
// block: 32 d x 64 pixels, 256 threads, thread = 2d x 4p x 4 gates
__global__ __launch_bounds__(256) void enc_step(
    const float* __restrict__ enc_in,
    const float* __restrict__ eWf, const float* __restrict__ ebf,
    const float* __restrict__ eWi, const float* __restrict__ ebi,
    const float* __restrict__ eWc, const float* __restrict__ ebc,
    const float* __restrict__ eWo, const float* __restrict__ ebo,
    int t, int inSel, int outSel)
{
    __shared__ __align__(16) float sW[16][4][32];
    __shared__ __align__(16) float sX[16][64];

    const float* h_in  = (inSel==0) ? g_hA : g_hB;
    float*       h_out = (outSel==0) ? g_hA : ((outSel==1) ? g_hB : g_hhist[0]);

    int b  = blockIdx.z;
    int d0 = blockIdx.y * 32;
    int p0 = blockIdx.x * 64;

    int tid = threadIdx.x;
    int dg = tid >> 4;    // 0..15 -> d pair
    int pg = tid & 15;    // 0..15 -> pixel quad

    const float* Wp0 = eWf; const float* Wp1 = eWi; const float* Wp2 = eWc; const float* Wp3 = eWo;
    const float* xt = enc_in + ((size_t)(b*TE + t))*CIN*HW;
    const float* hb = h_in + (size_t)b*HD*HW;

    float acc[4][2][4];
    #pragma unroll
    for (int g=0; g<4; g++)
        #pragma unroll
        for (int j=0; j<2; j++)
            #pragma unroll
            for (int pp=0; pp<4; pp++) acc[g][j][pp]=0.f;

    for (int k0 = 0; k0 < CE; k0 += 16) {
        // weights: 16k x 4g x 32d = 2048 elems
        #pragma unroll
        for (int l = 0; l < 8; l++) {
            int idx = tid + l*256;
            int k   = idx >> 7;
            int rem = idx & 127;
            int g   = rem >> 5;
            int dl  = rem & 31;
            const float* Wg = (g==0)?Wp0:((g==1)?Wp1:((g==2)?Wp2:Wp3));
            sW[k][g][dl] = Wg[(k0+k)*HD + d0 + dl];
        }
        // x tile: 16k x 64p
        #pragma unroll
        for (int l = 0; l < 4; l++) {
            int idx = tid + l*256;
            int k = idx >> 6;
            int p = idx & 63;
            int c = k0 + k;
            sX[k][p] = (c < CIN) ? xt[c*HW + p0 + p] : hb[(c-CIN)*HW + p0 + p];
        }
        __syncthreads();
        #pragma unroll
        for (int k = 0; k < 16; k++) {
            float4 xv = *(const float4*)&sX[k][pg*4];
            #pragma unroll
            for (int g = 0; g < 4; g++) {
                float2 wv = *(const float2*)&sW[k][g][dg*2];
                acc[g][0][0] += wv.x*xv.x; acc[g][0][1] += wv.x*xv.y;
                acc[g][0][2] += wv.x*xv.z; acc[g][0][3] += wv.x*xv.w;
                acc[g][1][0] += wv.y*xv.x; acc[g][1][1] += wv.y*xv.y;
                acc[g][1][2] += wv.y*xv.z; acc[g][1][3] += wv.y*xv.w;
            }
        }
        __syncthreads();
    }

    #pragma unroll
    for (int j = 0; j < 2; j++) {
        int d = d0 + dg*2 + j;
        float bf = ebf[d], bi = ebi[d], bc = ebc[d], bo = ebo[d];
        #pragma unroll
        for (int pp = 0; pp < 4; pp++) {
            int p = p0 + pg*4 + pp;
            size_t idx = ((size_t)b*HD + d)*HW + p;
            float f  = sigmf(acc[0][j][pp] + bf);
            float ii = sigmf(acc[1][j][pp] + bi);
            float gg = tanhf(acc[2][j][pp] + bc);
            float o  = sigmf(acc[3][j][pp] + bo);
            float cn = g_c[idx]*f + ii*gg;
            g_c[idx]   = cn;
            h_out[idx] = tanhf(cn)*o;
        }
    }
}

// ---------------------------------------------------------------- decoder step
// f,i,g: 3x3 conv (C=104 -> 96) over xc=[dec_in[b,t];h];  o: channel-linear
// block: 16x16 spatial x 16 d-channels, 256 threads, thread = 4px x 4d x 4 gates
__global__ __launch_bounds__(256) void dec_step(
    const float* __restrict__ dec_in,
    const float* __restrict__ dKf, const float* __restrict__ dbf,
    const float* __restrict__ dKi, const float* __restrict__ dbi,
    const float* __restrict__ dKc, const float* __restrict__ dbc,
    const float* __restrict__ dWo, const float* __restrict__ dbo,
    int t)
{
    __shared__ __align__(16) float sXT[8][18][20];
    __shared__ __align__(16) float sWc[8][9][3][16];
    __shared__ __align__(16) float sWo[8][16];

    const float* h_in  = g_hhist[t];
    float*       h_out = g_hhist[t+1];

    int b  = blockIdx.z;
    int d0 = blockIdx.y * 16;
    int ty = blockIdx.x >> 2, tx = blockIdx.x & 3;
    int y0 = ty*16, x0 = tx*16;

    int tid = threadIdx.x;
    int dq = tid >> 6;      // d base = dq*4
    int pq = tid & 63;
    int r  = pq >> 2;       // 0..15 output row
    int q  = pq & 3;        // x quad

    const float* xt = dec_in + ((size_t)(b*TD + t))*COUT*HW;
    const float* hb = h_in + (size_t)b*HD*HW;

    float accC[3][4][4];
    float accO[4][4];
    #pragma unroll
    for (int g=0; g<3; g++)
        #pragma unroll
        for (int j=0; j<4; j++)
            #pragma unroll
            for (int pp=0; pp<4; pp++) accC[g][j][pp]=0.f;
    #pragma unroll
    for (int j=0; j<4; j++)
        #pragma unroll
        for (int pp=0; pp<4; pp++) accO[j][pp]=0.f;

    for (int c0 = 0; c0 < CD; c0 += 8) {
        // x tile with halo: 8c x 18 x 18 (zero pad at image borders)
        for (int idx = tid; idx < 8*18*18; idx += 256) {
            int cl  = idx / 324;
            int rem = idx - cl*324;
            int rr  = rem / 18;
            int cc  = rem - rr*18;
            int c = c0 + cl;
            int y = y0 - 1 + rr, x = x0 - 1 + cc;
            float v = 0.f;
            if ((unsigned)y < 64u && (unsigned)x < 64u)
                v = (c < COUT) ? xt[c*HW + y*64 + x] : hb[(size_t)(c-COUT)*HW + y*64 + x];
            sXT[cl][rr][cc] = v;
        }
        // weights: conv 8c x 9tap x 3g x 16d + o 8c x 16d
        for (int idx = tid; idx < 3584; idx += 256) {
            if (idx < 3456) {
                int cl  = idx / 432;
                int rem = idx - cl*432;
                int tap = rem / 48;
                int r2  = rem - tap*48;
                int g   = r2 >> 4;
                int dl  = r2 & 15;
                const float* Kg = (g==0)?dKf:((g==1)?dKi:dKc);
                sWc[cl][tap][g][dl] = Kg[((size_t)(d0+dl)*CD + (c0+cl))*9 + tap];
            } else {
                int i2 = idx - 3456;
                int cl = i2 >> 4;
                int dl = i2 & 15;
                sWo[cl][dl] = dWo[(c0+cl)*HD + d0 + dl];
            }
        }
        __syncthreads();

        for (int cl = 0; cl < 8; cl++) {
            float4 wo4 = *(const float4*)&sWo[cl][dq*4];
            #pragma unroll
            for (int ky = 0; ky < 3; ky++) {
                float xr[6];
                {
                    const float* row = &sXT[cl][r+ky][q*4];
                    float4 a  = *(const float4*)row;
                    float2 bx = *(const float2*)(row+4);
                    xr[0]=a.x; xr[1]=a.y; xr[2]=a.z; xr[3]=a.w; xr[4]=bx.x; xr[5]=bx.y;
                }
                if (ky == 1) {  // center pixel for the linear o-gate
                    #pragma unroll
                    for (int pp=0; pp<4; pp++) {
                        float xc = xr[pp+1];
                        accO[0][pp] += wo4.x*xc; accO[1][pp] += wo4.y*xc;
                        accO[2][pp] += wo4.z*xc; accO[3][pp] += wo4.w*xc;
                    }
                }
                #pragma unroll
                for (int kx = 0; kx < 3; kx++) {
                    int tap = ky*3 + kx;
                    #pragma unroll
                    for (int g = 0; g < 3; g++) {
                        float4 w4 = *(const float4*)&sWc[cl][tap][g][dq*4];
                        #pragma unroll
                        for (int pp=0; pp<4; pp++) {
                            float xv = xr[kx+pp];
                            accC[g][0][pp] += w4.x*xv;
                            accC[g][1][pp] += w4.y*xv;
                            accC[g][2][pp] += w4.z*xv;
                            accC[g][3][pp] += w4.w*xv;
                        }
                    }
                }
            }
        }
        __syncthreads();
    }

    #pragma unroll
    for (int j = 0; j < 4; j++) {
        int d = d0 + dq*4 + j;
        float bf = dbf[d], bi = dbi[d], bc = dbc[d], bo = dbo[d];
        #pragma unroll
        for (int pp = 0; pp < 4; pp++) {
            int y = y0 + r, x = x0 + q*4 + pp;
            size_t idx = ((size_t)b*HD + d)*HW + y*64 + x;
            float f  = sigmf(accC[0][j][pp] + bf);
            float ii = sigmf(accC[1][j][pp] + bi);
            float gg = tanhf(accC[2][j][pp] + bc);
            float o  = sigmf(accO[j][pp]    + bo);
            float cn = g_c[idx]*f + ii*gg;
            g_c[idx]   = cn;
            h_out[idx] = tanhf(cn)*o;
        }
    }
}

// ---------------------------------------------------------------- deferred output head
// out[b,t,oc] = conv(h_t, Kp)[oc] + bp[oc]   (96 -> 8, 3x3), fully time-parallel
__global__ __launch_bounds__(256) void final_out(float* __restrict__ out)
{
    __shared__ __align__(16) float sX2[8][18][20];
    __shared__ __align__(16) float sW2[8][9][8];

    int b = blockIdx.z;
    int t = blockIdx.y;
    int ty = blockIdx.x >> 2, tx = blockIdx.x & 3;
    int y0 = ty*16, x0 = tx*16;

    const float* hb = g_hhist[t+1] + (size_t)b*HD*HW;

    int tid = threadIdx.x;
    int oq = tid >> 6;      // oc base = oq*2
    int pq = tid & 63;
    int r  = pq >> 2, q = pq & 3;

    float acc[2][4];
    #pragma unroll
    for (int j=0;j<2;j++)
        #pragma unroll
        for (int pp=0;pp<4;pp++) acc[j][pp]=0.f;

    for (int c0 = 0; c0 < HD; c0 += 8) {
        for (int idx = tid; idx < 8*18*18; idx += 256) {
            int cl  = idx / 324;
            int rem = idx - cl*324;
            int rr  = rem / 18;
            int cc  = rem - rr*18;
            int y = y0-1+rr, x = x0-1+cc;
            float v = 0.f;
            if ((unsigned)y < 64u && (unsigned)x < 64u)
                v = hb[(size_t)(c0+cl)*HW + y*64 + x];
            sX2[cl][rr][cc] = v;
        }
        for (int idx = tid; idx < 576; idx += 256) {
            int cl  = idx / 72;
            int rem = idx - cl*72;
            int tap = rem >> 3;
            int oc  = rem & 7;
            sW2[cl][tap][oc] = g_Kp[((size_t)oc*HD + (c0+cl))*9 + tap];
        }
        __syncthreads();
        for (int cl = 0; cl < 8; cl++) {
            #pragma unroll
            for (int ky = 0; ky < 3; ky++) {
                const float* row = &sX2[cl][r+ky][q*4];
                float4 a  = *(const float4*)row;
                float2 bx = *(const float2*)(row+4);
                float xr[6] = {a.x, a.y, a.z, a.w, bx.x, bx.y};
                #pragma unroll
                for (int kx = 0; kx < 3; kx++) {
                    float2 w2 = *(const float2*)&sW2[cl][ky*3+kx][oq*2];
                    #pragma unroll
                    for (int pp=0; pp<4; pp++) {
                        acc[0][pp] += w2.x*xr[kx+pp];
                        acc[1][pp] += w2.y*xr[kx+pp];
                    }
                }
            }
        }
        __syncthreads();
    }

    #pragma unroll
    for (int j=0; j<2; j++) {
        int oc = oq*2 + j;
        float bb = g_bp[oc];
        #pragma unroll
        for (int pp=0; pp<4; pp++) {
            int y = y0+r, x = x0+q*4+pp;
            out[(((size_t)(b*TD + t))*COUT + oc)*HW + y*64 + x] = acc[j][pp] + bb;
        }
    }
}

// ----------------------------------------------------------------
extern "C" void kernel_launch(void* const* d_in, const int* in_sizes, int n_in,
                              void* d_out, int out_size) {
    const float* enc_in = (const float*)d_in[0];
    const float* dec_in = (const float*)d_in[1];
    const float* eWf = (const float*)d_in[2];  const float* ebf = (const float*)d_in[3];
    const float* eWi = (const float*)d_in[4];  const float* ebi = (const float*)d_in[5];
    const float* eWc = (const float*)d_in[6];  const float* ebc = (const float*)d_in[7];
    const float* eWo = (const float*)d_in[8];  const float* ebo = (const float*)d_in[9];
    const float* dKf = (const float*)d_in[10]; const float* dbf = (const float*)d_in[11];
    const float* dKi = (const float*)d_in[12]; const float* dbi = (const float*)d_in[13];
    const float* dKc = (const float*)d_in[14]; const float* dbc = (const float*)d_in[15];
    const float* dWo = (const float*)d_in[16]; const float* dbo = (const float*)d_in[17];
    const float* oK  = (const float*)d_in[18]; const float* ob  = (const float*)d_in[19];
    const float* lW  = (const float*)d_in[20]; const float* lb  = (const float*)d_in[21];
    float* out = (float*)d_out;

    zero_kernel<<<1024, 256>>>();
    kp_kernel<<<(COUT*HD*9 + 255)/256, 256>>>(lW, oK, ob, lb);

    dim3 egrid(HW/64, HD/32, B);   // 64 x 3 x 8
    for (int t = 0; t < TE; t++) {
        int inSel  = t & 1;
        int outSel = (t == TE-1) ? 2 : ((t+1) & 1);
        enc_step<<<egrid, 256>>>(enc_in, eWf, ebf, eWi, ebi, eWc, ebc, eWo, ebo,
                                 t, inSel, outSel);
    }

    dim3 dgrid(16, HD/16, B);      // 16 x 6 x 8
    for (int t = 0; t < TD; t++)
        dec_step<<<dgrid, 256>>>(dec_in, dKf, dbf, dKi, dbi, dKc, dbc, dWo, dbo, t);

    dim3 fgrid(16, TD, B);         // 16 x 12 x 8
    final_out<<<fgrid, 256>>>(out);
}

// round 16
// speedup vs baseline: 1.0138x; 1.0138x over previous
#include <cuda_runtime.h>
#include <math.h>

#define B 8
#define TE 12
#define TD 12
#define CIN 16
#define HD 96
#define COUT 8
#define CD 104   /* COUT + HD */
#define CE 112   /* CIN + HD */
#define HW 4096
#define NSTATE (B*HD*HW)   /* 3,145,728 */

// ---- scratch (device globals: no allocation in kernel_launch) ----
__device__ float g_c[NSTATE];
__device__ float g_hA[NSTATE];
__device__ float g_hB[NSTATE];
__device__ float g_hhist[13][NSTATE];   // [0]=encoder final h, [t+1]=decoder h_t
__device__ float g_Kp[COUT*HD*9];       // folded oK . lW
__device__ float g_bp[COUT];

__device__ __forceinline__ float sigmf(float x) { return 1.0f/(1.0f + expf(-x)); }

// ---- packed f32x2 helpers (FFMA2: dual-rate fp32 FMA, ptxas never emits it) ----
__device__ __forceinline__ void ffma2(float2 &d, const float2 &a, const float2 &b) {
    asm("fma.rn.f32x2 %0, %1, %2, %0;"
        : "+l"(*reinterpret_cast<unsigned long long*>(&d))
        : "l"(*reinterpret_cast<const unsigned long long*>(&a)),
          "l"(*reinterpret_cast<const unsigned long long*>(&b)));
}
__device__ __forceinline__ unsigned long long dup2(float w) {
    unsigned long long r;
    asm("mov.b64 %0, {%1, %1};" : "=l"(r) : "f"(w));
    return r;
}

// ---------------------------------------------------------------- zero init
__global__ void zero_kernel() {
    int n4 = NSTATE/4;
    float4 z = make_float4(0.f,0.f,0.f,0.f);
    for (int i = blockIdx.x*blockDim.x + threadIdx.x; i < n4; i += gridDim.x*blockDim.x) {
        ((float4*)g_c)[i]  = z;
        ((float4*)g_hA)[i] = z;
    }
}

// ---------------------------------------------------------------- fold output head
__global__ void kp_kernel(const float* __restrict__ lW, const float* __restrict__ oK,
                          const float* __restrict__ ob, const float* __restrict__ lb) {
    int idx = blockIdx.x*blockDim.x + threadIdx.x;
    if (idx < COUT*HD*9) {
        int oc  = idx / (HD*9);
        int rem = idx - oc*(HD*9);     // = hc*9 + tap
        float s = 0.f;
        for (int c = 0; c < CD; c++)
            s += lW[c*COUT + oc] * oK[c*HD*9 + rem];
        g_Kp[idx] = s;
    }
    if (idx < COUT) {
        float s = lb[idx];
        for (int c = 0; c < CD; c++) s += lW[c*COUT + idx]*ob[c];
        g_bp[idx] = s;
    }
}

// ---------------------------------------------------------------- encoder step
// gates[d,p] = sum_{c<112} W_g[c,d] * xc[c,p],  xc = [enc_in[b,t] ; h]
// block: 32 d x 64 pixels, 256 threads. Per thread: 2d x 4p x 4 gates.
// FFMA2 packing: over pixel pairs; weights stored DUPLICATED {w,w} in smem.
__global__ __launch_bounds__(256) void enc_step(
    const float* __restrict__ enc_in,
    const float* __restrict__ eWf, const float* __restrict__ ebf,
    const float* __restrict__ eWi, const float* __restrict__ ebi,
    const float* __restrict__ eWc, const float* __restrict__ ebc,
    const float* __restrict__ eWo, const float* __restrict__ ebo,
    int t, int inSel, int outSel)
{
    __shared__ __align__(16) float sWd[16][4][64];  // duplicated weights (16KB)
    __shared__ __align__(16) float sX[16][64];      // 4KB

    const float* h_in  = (inSel==0) ? g_hA : g_hB;
    float*       h_out = (outSel==0) ? g_hA : ((outSel==1) ? g_hB : g_hhist[0]);

    int b  = blockIdx.z;
    int d0 = blockIdx.y * 32;
    int p0 = blockIdx.x * 64;

    int tid = threadIdx.x;
    int dg = tid >> 4;    // 0..15 -> d pair
    int pg = tid & 15;    // 0..15 -> pixel quad

    const float* Wp0 = eWf; const float* Wp1 = eWi; const float* Wp2 = eWc; const float* Wp3 = eWo;
    const float* xt = enc_in + ((size_t)(b*TE + t))*CIN*HW;
    const float* hb = h_in + (size_t)b*HD*HW;

    float2 acc[4][2][2];   // gate, d(2), pixel-pair(2)
    #pragma unroll
    for (int g=0; g<4; g++)
        #pragma unroll
        for (int j=0; j<2; j++)
            #pragma unroll
            for (int pp=0; pp<2; pp++) acc[g][j][pp] = make_float2(0.f,0.f);

    for (int k0 = 0; k0 < CE; k0 += 16) {
        // weights: 16k x 4g x 32d unique, written duplicated
        #pragma unroll
        for (int l = 0; l < 8; l++) {
            int idx = tid + l*256;
            int k   = idx >> 7;
            int rem = idx & 127;
            int g   = rem >> 5;
            int dl  = rem & 31;
            const float* Wg = (g==0)?Wp0:((g==1)?Wp1:((g==2)?Wp2:Wp3));
            float w = Wg[(k0+k)*HD + d0 + dl];
            *reinterpret_cast<unsigned long long*>(&sWd[k][g][2*dl]) = dup2(w);
        }
        // x tile: 16k x 64p
        #pragma unroll
        for (int l = 0; l < 4; l++) {
            int idx = tid + l*256;
            int k = idx >> 6;
            int p = idx & 63;
            int c = k0 + k;
            sX[k][p] = (c < CIN) ? xt[c*HW + p0 + p] : hb[(c-CIN)*HW + p0 + p];
        }
        __syncthreads();
        #pragma unroll
        for (int k = 0; k < 16; k++) {
            float4 xv = *(const float4*)&sX[k][pg*4];
            float2 xp0 = make_float2(xv.x, xv.y);
            float2 xp1 = make_float2(xv.z, xv.w);
            #pragma unroll
            for (int g = 0; g < 4; g++) {
                float4 wq = *(const float4*)&sWd[k][g][dg*4];   // {w0,w0,w1,w1}
                float2 w0 = make_float2(wq.x, wq.y);
                float2 w1 = make_float2(wq.z, wq.w);
                ffma2(acc[g][0][0], w0, xp0); ffma2(acc[g][0][1], w0, xp1);
                ffma2(acc[g][1][0], w1, xp0); ffma2(acc[g][1][1], w1, xp1);
            }
        }
        __syncthreads();
    }

    #pragma unroll
    for (int j = 0; j < 2; j++) {
        int d = d0 + dg*2 + j;
        float bf = ebf[d], bi = ebi[d], bc = ebc[d], bo = ebo[d];
        #pragma unroll
        for (int pp = 0; pp < 4; pp++) {
            int half = pp & 1;
            float af = half ? acc[0][j][pp>>1].y : acc[0][j][pp>>1].x;
            float ai = half ? acc[1][j][pp>>1].y : acc[1][j][pp>>1].x;
            float ac = half ? acc[2][j][pp>>1].y : acc[2][j][pp>>1].x;
            float ao = half ? acc[3][j][pp>>1].y : acc[3][j][pp>>1].x;
            int p = p0 + pg*4 + pp;
            size_t idx = ((size_t)b*HD + d)*HW + p;
            float f  = sigmf(af + bf);
            float ii = sigmf(ai + bi);
            float gg = tanhf(ac + bc);
            float o  = sigmf(ao + bo);
            float cn = g_c[idx]*f + ii*gg;
            g_c[idx]   = cn;
            h_out[idx] = tanhf(cn)*o;
        }
    }
}

// ---------------------------------------------------------------- decoder step
// f,i,g: 3x3 conv (C=104 -> 96) over xc=[dec_in[b,t];h];  o: channel-linear
// block: 16x16 spatial x 16 d-channels, 256 threads. Per thread: 4px x 4d x 4 gates.
// FFMA2 packing: over d pairs (weights contiguous); x stored DUPLICATED {v,v}
// with row stride 36 floats (conflict-free for 8r x 4q phases).
__global__ __launch_bounds__(256) void dec_step(
    const float* __restrict__ dec_in,
    const float* __restrict__ dKf, const float* __restrict__ dbf,
    const float* __restrict__ dKi, const float* __restrict__ dbi,
    const float* __restrict__ dKc, const float* __restrict__ dbc,
    const float* __restrict__ dWo, const float* __restrict__ dbo,
    int t)
{
    __shared__ __align__(16) float sXd[8][18][36];     // duplicated x (20.25KB)
    __shared__ __align__(16) float sWc[8][9][3][16];   // 6.75KB
    __shared__ __align__(16) float sWo[8][16];         // 0.5KB

    const float* h_in  = g_hhist[t];
    float*       h_out = g_hhist[t+1];

    int b  = blockIdx.z;
    int d0 = blockIdx.y * 16;
    int ty = blockIdx.x >> 2, tx = blockIdx.x & 3;
    int y0 = ty*16, x0 = tx*16;

    int tid = threadIdx.x;
    int dq = tid >> 6;      // d base = dq*4
    int pq = tid & 63;
    int r  = pq >> 2;       // 0..15 output row
    int q  = pq & 3;        // x quad

    const float* xt = dec_in + ((size_t)(b*TD + t))*COUT*HW;
    const float* hb = h_in + (size_t)b*HD*HW;

    float2 accC[3][2][4];   // gate, d-pair, px
    float2 accO[2][4];
    #pragma unroll
    for (int g=0; g<3; g++)
        #pragma unroll
        for (int j=0; j<2; j++)
            #pragma unroll
            for (int pp=0; pp<4; pp++) accC[g][j][pp] = make_float2(0.f,0.f);
    #pragma unroll
    for (int j=0; j<2; j++)
        #pragma unroll
        for (int pp=0; pp<4; pp++) accO[j][pp] = make_float2(0.f,0.f);

    for (int c0 = 0; c0 < CD; c0 += 8) {
        // x tile with halo: 8c x 18 x 18, duplicated in pairs
        for (int idx = tid; idx < 8*18*18; idx += 256) {
            int cl  = idx / 324;
            int rem = idx - cl*324;
            int rr  = rem / 18;
            int cc  = rem - rr*18;
            int c = c0 + cl;
            int y = y0 - 1 + rr, x = x0 - 1 + cc;
            float v = 0.f;
            if ((unsigned)y < 64u && (unsigned)x < 64u)
                v = (c < COUT) ? xt[c*HW + y*64 + x] : hb[(size_t)(c-COUT)*HW + y*64 + x];
            *reinterpret_cast<unsigned long long*>(&sXd[cl][rr][2*cc]) = dup2(v);
        }
        // weights: conv 8c x 9tap x 3g x 16d + o 8c x 16d
        for (int idx = tid; idx < 3584; idx += 256) {
            if (idx < 3456) {
                int cl  = idx / 432;
                int rem = idx - cl*432;
                int tap = rem / 48;
                int r2  = rem - tap*48;
                int g   = r2 >> 4;
                int dl  = r2 & 15;
                const float* Kg = (g==0)?dKf:((g==1)?dKi:dKc);
                sWc[cl][tap][g][dl] = Kg[((size_t)(d0+dl)*CD + (c0+cl))*9 + tap];
            } else {
                int i2 = idx - 3456;
                int cl = i2 >> 4;
                int dl = i2 & 15;
                sWo[cl][dl] = dWo[(c0+cl)*HD + d0 + dl];
            }
        }
        __syncthreads();

        for (int cl = 0; cl < 8; cl++) {
            float4 woq = *(const float4*)&sWo[cl][dq*4];        // broadcast
            float2 wo01 = make_float2(woq.x, woq.y);
            float2 wo23 = make_float2(woq.z, woq.w);
            #pragma unroll
            for (int ky = 0; ky < 3; ky++) {
                float2 xb[6];
                #pragma unroll
                for (int m = 0; m < 3; m++) {
                    float4 v = *(const float4*)&sXd[cl][r+ky][8*q + 4*m];
                    xb[2*m]   = make_float2(v.x, v.y);   // {x,x}
                    xb[2*m+1] = make_float2(v.z, v.w);
                }
                if (ky == 1) {  // center pixel for the linear o-gate
                    #pragma unroll
                    for (int pp=0; pp<4; pp++) {
                        ffma2(accO[0][pp], wo01, xb[pp+1]);
                        ffma2(accO[1][pp], wo23, xb[pp+1]);
                    }
                }
                #pragma unroll
                for (int kx = 0; kx < 3; kx++) {
                    #pragma unroll
                    for (int g = 0; g < 3; g++) {
                        float4 wq = *(const float4*)&sWc[cl][ky*3+kx][g][dq*4];  // broadcast
                        float2 w01 = make_float2(wq.x, wq.y);
                        float2 w23 = make_float2(wq.z, wq.w);
                        #pragma unroll
                        for (int pp=0; pp<4; pp++) {
                            ffma2(accC[g][0][pp], w01, xb[kx+pp]);
                            ffma2(accC[g][1][pp], w23, xb[kx+pp]);
                        }
                    }
                }
            }
        }
        __syncthreads();
    }

    #pragma unroll
    for (int jp = 0; jp < 2; jp++) {
        #pragma unroll
        for (int half = 0; half < 2; half++) {
            int d = d0 + dq*4 + jp*2 + half;
            float bf = dbf[d], bi = dbi[d], bc = dbc[d], bo = dbo[d];
            #pragma unroll
            for (int pp = 0; pp < 4; pp++) {
                float af = half ? accC[0][jp][pp].y : accC[0][jp][pp].x;
                float ai = half ? accC[1][jp][pp].y : accC[1][jp][pp].x;
                float ac = half ? accC[2][jp][pp].y : accC[2][jp][pp].x;
                float ao = half ? accO[jp][pp].y    : accO[jp][pp].x;
                int y = y0 + r, x = x0 + q*4 + pp;
                size_t idx = ((size_t)b*HD + d)*HW + y*64 + x;
                float f  = sigmf(af + bf);
                float ii = sigmf(ai + bi);
                float gg = tanhf(ac + bc);
                float o  = sigmf(ao + bo);
                float cn = g_c[idx]*f + ii*gg;
                g_c[idx]   = cn;
                h_out[idx] = tanhf(cn)*o;
            }
        }
    }
}

// ---------------------------------------------------------------- deferred output head
// out[b,t,oc] = conv(h_t, Kp)[oc] + bp[oc]   (96 -> 8, 3x3), fully time-parallel
// FFMA2 packing over oc pairs; x duplicated like decoder.
__global__ __launch_bounds__(256) void final_out(float* __restrict__ out)
{
    __shared__ __align__(16) float sX2[8][18][36];   // duplicated
    __shared__ __align__(16) float sW2[8][9][8];

    int b = blockIdx.z;
    int t = blockIdx.y;
    int ty = blockIdx.x >> 2, tx = blockIdx.x & 3;
    int y0 = ty*16, x0 = tx*16;

    const float* hb = g_hhist[t+1] + (size_t)b*HD*HW;

    int tid = threadIdx.x;
    int oq = tid >> 6;      // oc pair index (oc = oq*2, oq*2+1)
    int pq = tid & 63;
    int r  = pq >> 2, q = pq & 3;

    float2 acc2[4];          // per px: {oc0, oc1}
    #pragma unroll
    for (int pp=0;pp<4;pp++) acc2[pp] = make_float2(0.f,0.f);

    for (int c0 = 0; c0 < HD; c0 += 8) {
        for (int idx = tid; idx < 8*18*18; idx += 256) {
            int cl  = idx / 324;
            int rem = idx - cl*324;
            int rr  = rem / 18;
            int cc  = rem - rr*18;
            int y = y0-1+rr, x = x0-1+cc;
            float v = 0.f;
            if ((unsigned)y < 64u && (unsigned)x < 64u)
                v = hb[(size_t)(c0+cl)*HW + y*64 + x];
            *reinterpret_cast<unsigned long long*>(&sX2[cl][rr][2*cc]) = dup2(v);
        }
        for (int idx = tid; idx < 576; idx += 256) {
            int cl  = idx / 72;
            int rem = idx - cl*72;
            int tap = rem >> 3;
            int oc  = rem & 7;
            sW2[cl][tap][oc] = g_Kp[((size_t)oc*HD + (c0+cl))*9 + tap];
        }
        __syncthreads();
        for (int cl = 0; cl < 8; cl++) {
            #pragma unroll
            for (int ky = 0; ky < 3; ky++) {
                float2 xb[6];
                #pragma unroll
                for (int m = 0; m < 3; m++) {
                    float4 v = *(const float4*)&sX2[cl][r+ky][8*q + 4*m];
                    xb[2*m]   = make_float2(v.x, v.y);
                    xb[2*m+1] = make_float2(v.z, v.w);
                }
                #pragma unroll
                for (int kx = 0; kx < 3; kx++) {
                    float2 w2 = *(const float2*)&sW2[cl][ky*3+kx][oq*2];  // {w_oc0, w_oc1}
                    #pragma unroll
                    for (int pp=0; pp<4; pp++)
                        ffma2(acc2[pp], w2, xb[kx+pp]);
                }
            }
        }
        __syncthreads();
    }

    float b0 = g_bp[oq*2], b1 = g_bp[oq*2+1];
    #pragma unroll
    for (int pp=0; pp<4; pp++) {
        int y = y0+r, x = x0+q*4+pp;
        size_t base = ((size_t)(b*TD + t))*COUT*HW + (size_t)y*64 + x;
        out[base + (size_t)(oq*2  )*HW] = acc2[pp].x + b0;
        out[base + (size_t)(oq*2+1)*HW] = acc2[pp].y + b1;
    }
}

// ----------------------------------------------------------------
extern "C" void kernel_launch(void* const* d_in, const int* in_sizes, int n_in,
                              void* d_out, int out_size) {
    const float* enc_in = (const float*)d_in[0];
    const float* dec_in = (const float*)d_in[1];
    const float* eWf = (const float*)d_in[2];  const float* ebf = (const float*)d_in[3];
    const float* eWi = (const float*)d_in[4];  const float* ebi = (const float*)d_in[5];
    const float* eWc = (const float*)d_in[6];  const float* ebc = (const float*)d_in[7];
    const float* eWo = (const float*)d_in[8];  const float* ebo = (const float*)d_in[9];
    const float* dKf = (const float*)d_in[10]; const float* dbf = (const float*)d_in[11];
    const float* dKi = (const float*)d_in[12]; const float* dbi = (const float*)d_in[13];
    const float* dKc = (const float*)d_in[14]; const float* dbc = (const float*)d_in[15];
    const float* dWo = (const float*)d_in[16]; const float* dbo = (const float*)d_in[17];
    const float* oK  = (const float*)d_in[18]; const float* ob  = (const float*)d_in[19];
    const float* lW  = (const float*)d_in[20]; const float* lb  = (const float*)d_in[21];
    float* out = (float*)d_out;

    zero_kernel<<<1024, 256>>>();
    kp_kernel<<<(COUT*HD*9 + 255)/256, 256>>>(lW, oK, ob, lb);

    dim3 egrid(HW/64, HD/32, B);   // 64 x 3 x 8
    for (int t = 0; t < TE; t++) {
        int inSel  = t & 1;
        int outSel = (t == TE-1) ? 2 : ((t+1) & 1);
        enc_step<<<egrid, 256>>>(enc_in, eWf, ebf, eWi, ebi, eWc, ebc, eWo, ebo,
                                 t, inSel, outSel);
    }

    dim3 dgrid(16, HD/16, B);      // 16 x 6 x 8
    for (int t = 0; t < TD; t++)
        dec_step<<<dgrid, 256>>>(dec_in, dKf, dbf, dKi, dbi, dKc, dbc, dWo, dbo, t);

    dim3 fgrid(16, TD, B);         // 16 x 12 x 8
    final_out<<<fgrid, 256>>>(out);
}